// round 1
// baseline (speedup 1.0000x reference)
#include <cuda_runtime.h>
#include <math.h>

typedef unsigned long long ull;

#define BB 16
#define TT 2048
#define DD 1280
#define BT (BB*TT)          // 32768
#define GCTA 128
#define ESL (DD/GCTA)       // 10 rows of W_h per CTA

// -------- scratch (static __device__ — no runtime allocation) --------
__device__ float g_xproj[BT*DD];     // silu(x @ W_in^T[:, :D])   layout (B,T,D) rows b*T+t
__device__ float g_sz[BT*DD];        // silu(x @ W_in^T[:, D:])   layout (B,T,D)
__device__ float g_xpre[BT*DD];      // x_proj @ W_x^T + b        layout (T,B,D) rows t*B+b
__device__ float g_outpre[BT*DD];    // h_t * silu(z)             layout (T,B,D)
__device__ float g_h[2][BB*DD];      // double-buffered hidden state
__device__ ull   g_bar;              // global barrier counter (monotonic within a launch)

// -------- packed f32x2 helpers (FFMA2: 2 MACs/lane, only reachable via PTX) --------
__device__ __forceinline__ ull ffma2(ull a, ull b, ull c){
    ull d; asm("fma.rn.f32x2 %0, %1, %2, %3;" : "=l"(d) : "l"(a), "l"(b), "l"(c)); return d;
}
__device__ __forceinline__ ull pk2(float x){
    ull d; asm("mov.b64 %0, {%1, %1};" : "=l"(d) : "f"(x)); return d;
}
__device__ __forceinline__ float2 unpk(ull v){
    float2 r; asm("mov.b64 {%0, %1}, %2;" : "=f"(r.x), "=f"(r.y) : "l"(v)); return r;
}
__device__ __forceinline__ float silu_f(float v){ return v * (1.f/(1.f + __expf(-v))); }

// -------- prologue: zero h0 and the barrier counter (runs every launch/replay) --------
__global__ void reset_kernel(){
    int i = blockIdx.x*blockDim.x + threadIdx.x;
    if (i == 0) g_bar = 0ULL;
    if (i < BB*DD) g_h[0][i] = 0.f;
}

// ============================================================================
// SGEMM: C = A(MxK) * Bw^T(NxK), K=1280 fixed. 128x128 tile, BK=16, 256 thr,
// 8x8 per thread, FFMA2 accumulators.
// MODE 0: epilogue silu -> g_xproj (n<D) / g_sz (n>=D)         [GEMM1, N=2560]
// MODE 1: epilogue +bias, permute rows (b*T+t)->(t*B+b) -> g_xpre [GEMM2]
// MODE 2: epilogue permute rows (t*B+b)->(b,t) -> dout            [GEMM3]
// ============================================================================
template<int MODE>
__global__ __launch_bounds__(256,2)
void gemm_kernel(const float* __restrict__ A, const float* __restrict__ Bw,
                 const float* __restrict__ bias, float* __restrict__ dout){
    __shared__ float As[16][132];
    __shared__ float Bs[16][132];
    const int tid = threadIdx.x;
    const int m0 = blockIdx.x*128, n0 = blockIdx.y*128;
    const int tx = tid & 15, ty = tid >> 4;

    ull acc[8][4];
    #pragma unroll
    for (int i=0;i<8;i++){
        #pragma unroll
        for(int j=0;j<4;j++) acc[i][j]=0ULL;
    }

    for (int kt=0; kt<DD; kt+=16){
        #pragma unroll
        for (int r=0;r<2;r++){
            int f = tid + r*256;
            int row = f >> 2, c4 = (f & 3) << 2;
            float4 va = *(const float4*)(A  + (size_t)(m0+row)*DD + kt + c4);
            As[c4+0][row]=va.x; As[c4+1][row]=va.y; As[c4+2][row]=va.z; As[c4+3][row]=va.w;
            float4 vb = *(const float4*)(Bw + (size_t)(n0+row)*DD + kt + c4);
            Bs[c4+0][row]=vb.x; Bs[c4+1][row]=vb.y; Bs[c4+2][row]=vb.z; Bs[c4+3][row]=vb.w;
        }
        __syncthreads();
        #pragma unroll
        for (int k=0;k<16;k++){
            float4 a0 = *(const float4*)&As[k][ty*8];
            float4 a1 = *(const float4*)&As[k][ty*8+4];
            ulonglong2 b0 = *(const ulonglong2*)&Bs[k][tx*8];
            ulonglong2 b1 = *(const ulonglong2*)&Bs[k][tx*8+4];
            ull bb0 = b0.x, bb1 = b0.y, bb2 = b1.x, bb3 = b1.y;
            float av[8] = {a0.x,a0.y,a0.z,a0.w,a1.x,a1.y,a1.z,a1.w};
            #pragma unroll
            for (int i=0;i<8;i++){
                ull ad = pk2(av[i]);
                acc[i][0] = ffma2(ad, bb0, acc[i][0]);
                acc[i][1] = ffma2(ad, bb1, acc[i][1]);
                acc[i][2] = ffma2(ad, bb2, acc[i][2]);
                acc[i][3] = ffma2(ad, bb3, acc[i][3]);
            }
        }
        __syncthreads();
    }

    // epilogue
    #pragma unroll
    for (int i=0;i<8;i++){
        int m = m0 + ty*8 + i;
        #pragma unroll
        for (int j=0;j<4;j++){
            float2 v = unpk(acc[i][j]);
            int n = n0 + tx*8 + j*2;
            if (MODE == 0){
                float2 s; s.x = silu_f(v.x); s.y = silu_f(v.y);
                if (n < DD) *(float2*)&g_xproj[(size_t)m*DD + n] = s;
                else        *(float2*)&g_sz   [(size_t)m*DD + (n-DD)] = s;
            } else if (MODE == 1){
                float2 s; s.x = v.x + bias[n]; s.y = v.y + bias[n+1];
                int ro = ((m & (TT-1)) << 4) | (m >> 11);   // (b*T+t) -> t*16+b
                *(float2*)&g_xpre[(size_t)ro*DD + n] = s;
            } else {
                int b = m & 15, t = m >> 4;                 // row = t*16+b
                *(float2*)&dout[(size_t)b*TT*DD + (size_t)t*DD + n] = v;
            }
        }
    }
}

// ============================================================================
// Persistent recurrence kernel. 128 CTAs (<=148 SMs -> all co-resident),
// 256 threads. W_h e-slice (10x1280) lives in SMEM (layout [k][e], pad 12).
// Per step: h_new[b,e] = tanh(x_pre[t,b,e] + sum_d h[b,d]*W_h[e,d]);
// out_pre = h_new * silu(z). Global spin barrier between steps.
// dyn smem: Wsh 1280*12 + red 16*160 floats = 71680 B.
// ============================================================================
extern __shared__ float smem_dyn[];
__global__ __launch_bounds__(256,1)
void recur_kernel(const float* __restrict__ W_h, const float* __restrict__ xpre,
                  const float* __restrict__ sz, float* __restrict__ outpre,
                  float* __restrict__ dout_h){
    float* Wsh = smem_dyn;            // [1280][12], Wsh[d*12+e] = W_h[e0+e][d]
    float* red = smem_dyn + DD*12;    // [16 chunks][16 b][10 e]
    const int tid = threadIdx.x;
    const int e0  = blockIdx.x * ESL;

    for (int idx = tid; idx < ESL*DD; idx += 256){
        int e = idx / DD, d = idx - e*DD;
        Wsh[d*12 + e] = W_h[(size_t)(e0+e)*DD + d];
    }
    __syncthreads();

    // warp w: b-group (w&3)*4, k-half (w>>2)*640. lane: bq=l>>3 (4 b), kq=l&7.
    // 8 consecutive lanes read 128B of one h row -> coalesced ld.cg.
    const int w = tid >> 5, l = tid & 31;
    const int b     = (w & 3)*4 + (l >> 3);
    const int khalf = w >> 2;
    const int kq    = l & 7;
    const int chunk = khalf*8 + kq;    // 16 k-chunks of 80
    const int rb = tid / 10, re = tid - rb*10;  // epilogue mapping (tid<160)

    for (int t=0; t<TT; t++){
        const float* hp = g_h[t&1] + b*DD + khalf*640 + kq*4;
        ull a0=0,a1=0,a2=0,a3=0,a4=0;
        #pragma unroll 5
        for (int it=0; it<20; it++){
            float4 h4 = __ldcg((const float4*)(hp + it*32));
            int k0 = khalf*640 + it*32 + kq*4;
            const float* wr = &Wsh[k0*12];
            #pragma unroll
            for (int c=0;c<4;c++){
                float hv = (c==0)?h4.x:((c==1)?h4.y:((c==2)?h4.z:h4.w));
                ull hd = pk2(hv);
                const float* wc = wr + c*12;                 // 48B stride -> 16B aligned
                ulonglong2 w01 = *(const ulonglong2*)(wc);
                ulonglong2 w23 = *(const ulonglong2*)(wc+4);
                ull        w4v = *(const ull*)(wc+8);
                a0 = ffma2(hd, w01.x, a0);
                a1 = ffma2(hd, w01.y, a1);
                a2 = ffma2(hd, w23.x, a2);
                a3 = ffma2(hd, w23.y, a3);
                a4 = ffma2(hd, w4v,   a4);
            }
        }
        ull* rp = (ull*)(red + chunk*160 + b*10);
        rp[0]=a0; rp[1]=a1; rp[2]=a2; rp[3]=a3; rp[4]=a4;
        __syncthreads();

        if (tid < 160){
            float s = 0.f;
            #pragma unroll
            for (int c=0;c<16;c++) s += red[c*160 + rb*10 + re];
            float xp = xpre[(size_t)(t*BB + rb)*DD + e0 + re];
            float h  = tanhf(xp + s);
            __stcg(&g_h[(t+1)&1][rb*DD + e0 + re], h);
            float zz = sz[(size_t)rb*TT*DD + (size_t)t*DD + e0 + re];
            outpre[(size_t)(t*BB + rb)*DD + e0 + re] = h * zz;
            if (dout_h != nullptr && t == TT-1) dout_h[rb*DD + e0 + re] = h;
        }
        __threadfence();
        __syncthreads();
        if (tid == 0){
            atomicAdd(&g_bar, 1ULL);
            ull target = (ull)(t+1) * (ull)gridDim.x;
            int guard = 0;
            while (*((volatile ull*)&g_bar) < target){
                if (++guard > 30000) break;   // anti-hang bailout; legit waits are <<1ms
                __nanosleep(64);
            }
            __threadfence();
        }
        __syncthreads();
    }
}

// ============================================================================
extern "C" void kernel_launch(void* const* d_in, const int* in_sizes, int n_in,
                              void* d_out, int out_size){
    const float* x     = (const float*)d_in[0];   // (16,2048,1280)
    const float* W_in  = (const float*)d_in[1];   // (2560,1280)
    const float* W_out = (const float*)d_in[2];   // (1280,1280)
    const float* W_x   = (const float*)d_in[3];   // (1280,1280)
    const float* W_h   = (const float*)d_in[4];   // (1280,1280)
    const float* bias  = (const float*)d_in[5];   // (1280,)
    float* out = (float*)d_out;

    cudaFuncSetAttribute(recur_kernel, cudaFuncAttributeMaxDynamicSharedMemorySize, 71680);

    float* dout_h = (out_size >= BT*DD + BB*DD) ? (out + (size_t)BT*DD) : nullptr;

    // device-symbol pointers for scratch (passed to GEMMs as A operands)
    float* xproj_p; cudaGetSymbolAddress((void**)&xproj_p, g_xproj);
    float* xpre_p;  cudaGetSymbolAddress((void**)&xpre_p,  g_xpre);
    float* sz_p;    cudaGetSymbolAddress((void**)&sz_p,    g_sz);
    float* outpre_p;cudaGetSymbolAddress((void**)&outpre_p,g_outpre);

    reset_kernel<<<80, 256>>>();

    // GEMM1: xz = x @ W_in^T (fused silu on both halves)
    gemm_kernel<0><<<dim3(BT/128, (2*DD)/128), 256>>>(x, W_in, nullptr, nullptr);

    // GEMM2: x_pre = silu(xproj) @ W_x^T + b, stored (T,B,D)
    gemm_kernel<1><<<dim3(BT/128, DD/128), 256>>>(xproj_p, W_x, bias, nullptr);

    // Recurrence (persistent, 2048 steps)
    recur_kernel<<<GCTA, 256, 71680>>>(W_h, xpre_p, sz_p, outpre_p, dout_h);

    // GEMM3: out = out_pre @ W_out^T, permuted to (B,T,D) in d_out
    gemm_kernel<2><<<dim3(BT/128, DD/128), 256>>>(outpre_p, W_out, nullptr, out);
}

// round 2
// speedup vs baseline: 2.0400x; 2.0400x over previous
#include <cuda_runtime.h>
#include <math.h>

typedef unsigned long long ull;

#define BB 16
#define TT 2048
#define DD 1280
#define BT (BB*TT)          // 32768
#define GCTA 128
#define ESL 10              // e-rows of W_h per CTA
#define RSTRIDE 164         // padded reduction stride (floats)

// -------- scratch (static __device__ — no runtime allocation) --------
__device__ float g_xproj[BT*DD];     // silu(x @ W_in^T[:, :D])   rows b*T+t
__device__ float g_sz[BT*DD];        // silu(x @ W_in^T[:, D:])   rows b*T+t
__device__ float g_xpre[BT*DD];      // x_proj @ W_x^T + b        rows t*B+b
__device__ float g_outpre[BT*DD];    // h_t * silu(z)             rows t*B+b
__device__ float g_h[2][BB*DD];      // double-buffered hidden state
__device__ ull   g_bar;              // global barrier counter

// -------- packed f32x2 helpers --------
__device__ __forceinline__ ull ffma2(ull a, ull b, ull c){
    ull d; asm("fma.rn.f32x2 %0, %1, %2, %3;" : "=l"(d) : "l"(a), "l"(b), "l"(c)); return d;
}
__device__ __forceinline__ ull pk2(float x){
    ull d; asm("mov.b64 %0, {%1, %1};" : "=l"(d) : "f"(x)); return d;
}
__device__ __forceinline__ ull pkxy(float x, float y){
    ull d; asm("mov.b64 %0, {%1, %2};" : "=l"(d) : "f"(x), "f"(y)); return d;
}
__device__ __forceinline__ float2 unpk(ull v){
    float2 r; asm("mov.b64 {%0, %1}, %2;" : "=f"(r.x), "=f"(r.y) : "l"(v)); return r;
}
__device__ __forceinline__ float hadd(ull v){ float2 f = unpk(v); return f.x + f.y; }
__device__ __forceinline__ float silu_f(float v){ return v * (1.f/(1.f + __expf(-v))); }

// -------- prologue: zero h0 and the barrier counter --------
__global__ void reset_kernel(){
    int i = blockIdx.x*blockDim.x + threadIdx.x;
    if (i == 0) g_bar = 0ULL;
    if (i < BB*DD) g_h[0][i] = 0.f;
}

// ============================================================================
// SGEMM: C = A(MxK) * Bw^T(NxK), K=1280. 128x128 tile, BK=16, 256 thr,
// 8x8/thread (split 4+4 in m and n for conflict-free smem), FFMA2 accum,
// register double-buffered global loads.
// MODE 0: silu -> g_xproj (n<D) / g_sz (n>=D)
// MODE 1: +bias, permute rows (b*T+t)->(t*B+b) -> g_xpre
// MODE 2: permute rows (t*B+b)->(b,t) -> dout
// ============================================================================
template<int MODE>
__global__ __launch_bounds__(256,2)
void gemm_kernel(const float* __restrict__ A, const float* __restrict__ Bw,
                 const float* __restrict__ bias, float* __restrict__ dout){
    __shared__ float As[16][132];
    __shared__ float Bs[16][132];
    const int tid = threadIdx.x;
    const int m0 = blockIdx.x*128, n0 = blockIdx.y*128;
    const int tx = tid & 15, ty = tid >> 4;
    const int row0 = tid >> 2, row1 = row0 + 64;
    const int c4 = (tid & 3) << 2;

    const float* Ar0 = A  + (size_t)(m0+row0)*DD + c4;
    const float* Ar1 = A  + (size_t)(m0+row1)*DD + c4;
    const float* Br0 = Bw + (size_t)(n0+row0)*DD + c4;
    const float* Br1 = Bw + (size_t)(n0+row1)*DD + c4;

    float4 pa0 = *(const float4*)(Ar0);
    float4 pa1 = *(const float4*)(Ar1);
    float4 pb0 = *(const float4*)(Br0);
    float4 pb1 = *(const float4*)(Br1);

    ull acc[8][4];
    #pragma unroll
    for (int i=0;i<8;i++){
        #pragma unroll
        for (int j=0;j<4;j++) acc[i][j]=0ULL;
    }

    for (int kt=0; kt<DD; kt+=16){
        As[c4+0][row0]=pa0.x; As[c4+1][row0]=pa0.y; As[c4+2][row0]=pa0.z; As[c4+3][row0]=pa0.w;
        As[c4+0][row1]=pa1.x; As[c4+1][row1]=pa1.y; As[c4+2][row1]=pa1.z; As[c4+3][row1]=pa1.w;
        Bs[c4+0][row0]=pb0.x; Bs[c4+1][row0]=pb0.y; Bs[c4+2][row0]=pb0.z; Bs[c4+3][row0]=pb0.w;
        Bs[c4+0][row1]=pb1.x; Bs[c4+1][row1]=pb1.y; Bs[c4+2][row1]=pb1.z; Bs[c4+3][row1]=pb1.w;
        __syncthreads();

        if (kt + 16 < DD){
            pa0 = *(const float4*)(Ar0 + kt + 16);
            pa1 = *(const float4*)(Ar1 + kt + 16);
            pb0 = *(const float4*)(Br0 + kt + 16);
            pb1 = *(const float4*)(Br1 + kt + 16);
        }

        #pragma unroll
        for (int k=0;k<16;k++){
            float4 a0 = *(const float4*)&As[k][ty*4];
            float4 a1 = *(const float4*)&As[k][64 + ty*4];
            ulonglong2 bl = *(const ulonglong2*)&Bs[k][tx*4];
            ulonglong2 bh = *(const ulonglong2*)&Bs[k][64 + tx*4];
            float av[8] = {a0.x,a0.y,a0.z,a0.w, a1.x,a1.y,a1.z,a1.w};
            #pragma unroll
            for (int i=0;i<8;i++){
                ull ad = pk2(av[i]);
                acc[i][0] = ffma2(ad, bl.x, acc[i][0]);
                acc[i][1] = ffma2(ad, bl.y, acc[i][1]);
                acc[i][2] = ffma2(ad, bh.x, acc[i][2]);
                acc[i][3] = ffma2(ad, bh.y, acc[i][3]);
            }
        }
        __syncthreads();
    }

    // epilogue
    #pragma unroll
    for (int i=0;i<8;i++){
        int m = m0 + ((i<4) ? (ty*4 + i) : (64 + ty*4 + i - 4));
        #pragma unroll
        for (int j=0;j<4;j++){
            int n = n0 + ((j<2) ? (tx*4 + j*2) : (64 + tx*4 + (j-2)*2));
            float2 v = unpk(acc[i][j]);
            if (MODE == 0){
                float2 s; s.x = silu_f(v.x); s.y = silu_f(v.y);
                if (n < DD) *(float2*)&g_xproj[(size_t)m*DD + n] = s;
                else        *(float2*)&g_sz   [(size_t)m*DD + (n-DD)] = s;
            } else if (MODE == 1){
                float2 s; s.x = v.x + bias[n]; s.y = v.y + bias[n+1];
                int ro = ((m & (TT-1)) << 4) | (m >> 11);   // (b*T+t) -> t*16+b
                *(float2*)&g_xpre[(size_t)ro*DD + n] = s;
            } else {
                int b = m & 15, t = m >> 4;                 // row = t*16+b
                *(float2*)&dout[(size_t)b*TT*DD + (size_t)t*DD + n] = v;
            }
        }
    }
}

// ============================================================================
// Persistent recurrence. 128 CTAs, 256 thr. W_h slice [10][1280] in SMEM in
// NATURAL [e][k] layout: lanes read contiguous 128B per (e, it) -> 1 wavefront,
// conflict-free. Accumulate along k with FFMA2 (pairs of k). 16-way k-split
// reduction through padded smem. Global spin barrier per step.
// ============================================================================
extern __shared__ float smem_dyn[];
__global__ __launch_bounds__(256,1)
void recur_kernel(const float* __restrict__ W_h, const float* __restrict__ xpre,
                  const float* __restrict__ sz, float* __restrict__ outpre,
                  float* __restrict__ dout_h){
    float* Wsh = smem_dyn;              // [10][1280]
    float* red = smem_dyn + ESL*DD;     // [16][RSTRIDE]
    const int tid = threadIdx.x;
    const int e0  = blockIdx.x * ESL;

    {   // W_h rows e0..e0+9 are contiguous: straight float4 copy
        const float4* Wsrc = (const float4*)(W_h + (size_t)e0*DD);
        float4* Wdst = (float4*)Wsh;
        for (int idx = tid; idx < ESL*DD/4; idx += 256) Wdst[idx] = Wsrc[idx];
    }
    __syncthreads();

    const int w = tid >> 5, l = tid & 31;
    const int b     = (w & 3)*4 + (l >> 3);
    const int khalf = w >> 2;
    const int kq    = l & 7;
    const int chunk = khalf*8 + kq;                 // 16 k-chunks of 80
    const int rb = tid / 10, re = tid - rb*10;      // epilogue map (tid<160)
    const bool epi = (tid < 160);

    for (int t=0; t<TT; t++){
        // prefetch epilogue operands (consumed after ~1600cyc of compute)
        float xp = 0.f, zz = 0.f;
        if (epi){
            xp = xpre[(size_t)(t*BB + rb)*DD + e0 + re];
            zz = sz[(size_t)rb*TT*DD + (size_t)t*DD + e0 + re];
        }

        const float* hp = g_h[t&1] + b*DD + khalf*640 + kq*4;
        ull acc[10];
        #pragma unroll
        for (int e=0;e<10;e++) acc[e]=0ULL;

        #pragma unroll 2
        for (int it=0; it<20; it++){
            float4 h4 = __ldcg((const float4*)(hp + it*32));
            ull hd01 = pkxy(h4.x, h4.y);
            ull hd23 = pkxy(h4.z, h4.w);
            const float* wp = Wsh + khalf*640 + it*32 + kq*4;
            #pragma unroll
            for (int e=0;e<10;e++){
                ulonglong2 wv = *(const ulonglong2*)(wp + e*DD);  // contiguous 16B, no conflicts
                acc[e] = ffma2(hd01, wv.x, acc[e]);
                acc[e] = ffma2(hd23, wv.y, acc[e]);
            }
        }

        float* rp = red + chunk*RSTRIDE + b*10;
        #pragma unroll
        for (int e=0;e<10;e+=2){
            float2 v; v.x = hadd(acc[e]); v.y = hadd(acc[e+1]);
            *(float2*)(rp + e) = v;
        }
        __syncthreads();

        if (epi){
            float s = 0.f;
            #pragma unroll
            for (int c=0;c<16;c++) s += red[c*RSTRIDE + tid];
            float h = tanhf(xp + s);
            __stcg(&g_h[(t+1)&1][rb*DD + e0 + re], h);
            outpre[(size_t)(t*BB + rb)*DD + e0 + re] = h * zz;
            if (dout_h != nullptr && t == TT-1) dout_h[rb*DD + e0 + re] = h;
        }
        __threadfence();
        __syncthreads();
        if (tid == 0){
            atomicAdd(&g_bar, 1ULL);
            ull target = (ull)(t+1) * (ull)gridDim.x;
            int guard = 0;
            while (*((volatile ull*)&g_bar) < target){
                if (++guard > 60000) break;   // anti-hang bailout
                __nanosleep(32);
            }
            __threadfence();
        }
        __syncthreads();
    }
}

// ============================================================================
extern "C" void kernel_launch(void* const* d_in, const int* in_sizes, int n_in,
                              void* d_out, int out_size){
    const float* x     = (const float*)d_in[0];   // (16,2048,1280)
    const float* W_in  = (const float*)d_in[1];   // (2560,1280)
    const float* W_out = (const float*)d_in[2];   // (1280,1280)
    const float* W_x   = (const float*)d_in[3];   // (1280,1280)
    const float* W_h   = (const float*)d_in[4];   // (1280,1280)
    const float* bias  = (const float*)d_in[5];   // (1280,)
    float* out = (float*)d_out;

    const int recur_smem = (ESL*DD + 16*RSTRIDE) * 4;   // 61696 B
    cudaFuncSetAttribute(recur_kernel, cudaFuncAttributeMaxDynamicSharedMemorySize, recur_smem);

    float* dout_h = (out_size >= BT*DD + BB*DD) ? (out + (size_t)BT*DD) : nullptr;

    float* xproj_p; cudaGetSymbolAddress((void**)&xproj_p, g_xproj);
    float* xpre_p;  cudaGetSymbolAddress((void**)&xpre_p,  g_xpre);
    float* sz_p;    cudaGetSymbolAddress((void**)&sz_p,    g_sz);
    float* outpre_p;cudaGetSymbolAddress((void**)&outpre_p,g_outpre);

    reset_kernel<<<80, 256>>>();

    // GEMM1: xz = x @ W_in^T (fused silu on both halves)
    gemm_kernel<0><<<dim3(BT/128, (2*DD)/128), 256>>>(x, W_in, nullptr, nullptr);

    // GEMM2: x_pre = silu(xproj) @ W_x^T + b, stored (T,B,D)
    gemm_kernel<1><<<dim3(BT/128, DD/128), 256>>>(xproj_p, W_x, bias, nullptr);

    // Recurrence (persistent, 2048 steps)
    recur_kernel<<<GCTA, 256, recur_smem>>>(W_h, xpre_p, sz_p, outpre_p, dout_h);

    // GEMM3: out = out_pre @ W_out^T, permuted to (B,T,D) in d_out
    gemm_kernel<2><<<dim3(BT/128, DD/128), 256>>>(outpre_p, W_out, nullptr, out);
}